// round 9
// baseline (speedup 1.0000x reference)
#include <cuda_runtime.h>
#include <cuda_fp16.h>
#include <math.h>
#include <stdint.h>

#define B_  8192
#define DE_ 256
#define DA_ 32
#define F_  2048
#define H_  2048

// ---------------- scratch (device globals) ----------------
__device__ __half g_xfull[(size_t)B_ * 6144];   // [feat_o | feat_a | h0]
__device__ float  g_gsum[(size_t)B_ * 4096];    // r,z gates: gi+gh summed (bias incl)
__device__ float  g_ghn[(size_t)B_ * 2048];     // h_n gate (bias incl)
__device__ __half g_lasth[(size_t)B_ * 4096];   // [feat_post | h1]
__device__ __half g_Wrz[(size_t)4096 * 6144];   // [W_ih_rz | W_hh_rz]
__device__ __half g_Wihn[(size_t)2048 * 4096];
__device__ __half g_Whhn[(size_t)2048 * 2048];
__device__ __half g_envh[(size_t)B_ * 256];
__device__ __half g_pah[(size_t)B_ * 64];       // K padded 32 -> 64
__device__ __half g_Woph[(size_t)4096 * 256];   // [W_o ; W_post]
__device__ __half g_Wah[(size_t)2048 * 64];
__device__ __half g_W3h[(size_t)32 * 4096];

__device__ __forceinline__ uint32_t smem_u32(const void* p) {
    uint32_t a;
    asm("{ .reg .u64 t; cvta.to.shared.u64 t, %1; cvt.u32.u64 %0, t; }"
        : "=r"(a) : "l"(p));
    return a;
}

__device__ __forceinline__ void mma_fp16(float* c, const unsigned* a, const unsigned* b) {
    asm volatile(
        "mma.sync.aligned.m16n8k16.row.col.f32.f16.f16.f32 "
        "{%0,%1,%2,%3}, {%4,%5,%6,%7}, {%8,%9}, {%0,%1,%2,%3};"
        : "+f"(c[0]), "+f"(c[1]), "+f"(c[2]), "+f"(c[3])
        : "r"(a[0]), "r"(a[1]), "r"(a[2]), "r"(a[3]), "r"(b[0]), "r"(b[1]));
}

__device__ __forceinline__ float sigm(float x) { return 1.0f / (1.0f + expf(-x)); }

// ============ shared mainloop macro-free core pieces (4 warps, 64x64 warp tile) ============
#define GEMM4_PROLOG()                                                          \
    constexpr int BM = 128, BK = 64, LDH = 72, STAGES = 3;                      \
    constexpr int OPB = BM * LDH * 2;                                           \
    extern __shared__ __half smh[];                                             \
    const unsigned sA = smem_u32(smh);                                          \
    const unsigned sB = sA + STAGES * OPB;                                      \
    int bx, by;                                                                 \
    {                                                                           \
        const int id = blockIdx.y * gridDim.x + blockIdx.x;                     \
        const int cpg = 8 * gridDim.y;                                          \
        const int grp = id / cpg;                                               \
        const int rem = id % cpg;                                               \
        bx = grp * 8 + (rem & 7);                                               \
        by = rem >> 3;                                                          \
    }                                                                           \
    const int m0 = by * BM;                                                     \
    const int n0 = bx * BM;                                                     \
    const int tid = threadIdx.x;                                                \
    const int warp = tid >> 5;                                                  \
    const int lane = tid & 31;                                                  \
    const int wm = (warp & 1) * 64;                                             \
    const int wn = (warp >> 1) * 64;                                            \
    const int g = lane >> 3;                                                    \
    const int r8 = lane & 7;                                                    \
    const int aRow = (g & 1) * 8 + r8;                                          \
    const int aColH = (g >> 1) * 8;                                             \
    const int bRow = (g >> 1) * 8 + r8;                                         \
    const int bColH = (g & 1) * 8;                                              \
    float acc[4][8][4];                                                         \
    _Pragma("unroll")                                                           \
    for (int i = 0; i < 4; i++)                                                 \
        _Pragma("unroll")                                                       \
        for (int j = 0; j < 8; j++)                                             \
            _Pragma("unroll")                                                   \
            for (int v = 0; v < 4; v++) acc[i][j][v] = 0.0f;                    \
    auto issueStage = [&](int it, int stage) {                                  \
        if (it < kIters) {                                                      \
            const long k0 = (long)it * BK;                                      \
            const unsigned dA = sA + stage * OPB;                               \
            const unsigned dB = sB + stage * OPB;                               \
            _Pragma("unroll")                                                   \
            for (int i = 0; i < 8; i++) {                                       \
                const int ch = tid + i * 128;                                   \
                const int r = ch >> 3, c = ch & 7;                              \
                const __half* src = A + (long)(m0 + r) * lda + k0 + c * 8;      \
                const unsigned dst = dA + (unsigned)(r * LDH + c * 8) * 2u;     \
                asm volatile("cp.async.cg.shared.global [%0], [%1], 16;\n"      \
                             :: "r"(dst), "l"(src));                            \
            }                                                                   \
            _Pragma("unroll")                                                   \
            for (int i = 0; i < 8; i++) {                                       \
                const int ch = tid + i * 128;                                   \
                const int r = ch >> 3, c = ch & 7;                              \
                const __half* src = W + (long)(n0 + r) * ldw + k0 + c * 8;      \
                const unsigned dst = dB + (unsigned)(r * LDH + c * 8) * 2u;     \
                asm volatile("cp.async.cg.shared.global [%0], [%1], 16;\n"      \
                             :: "r"(dst), "l"(src));                            \
            }                                                                   \
        }                                                                       \
        asm volatile("cp.async.commit_group;\n");                               \
    };                                                                          \
    issueStage(0, 0);                                                           \
    issueStage(1, 1);                                                           \
    for (int it = 0; it < kIters; it++) {                                       \
        asm volatile("cp.async.wait_group 1;\n");                               \
        __syncthreads();                                                        \
        const int stage = it % STAGES;                                          \
        issueStage(it + 2, (it + 2) % STAGES);                                  \
        const unsigned baseA = sA + stage * OPB;                                \
        const unsigned baseB = sB + stage * OPB;                                \
        _Pragma("unroll")                                                       \
        for (int kk = 0; kk < BK; kk += 16) {                                   \
            unsigned a[4][4], b[8][2];                                          \
            _Pragma("unroll")                                                   \
            for (int mi = 0; mi < 4; mi++) {                                    \
                const unsigned addr =                                           \
                    baseA + (unsigned)(((wm + mi * 16 + aRow) * LDH + kk + aColH) << 1); \
                asm volatile(                                                   \
                    "ldmatrix.sync.aligned.m8n8.x4.shared.b16 {%0,%1,%2,%3}, [%4];" \
                    : "=r"(a[mi][0]), "=r"(a[mi][1]), "=r"(a[mi][2]), "=r"(a[mi][3]) \
                    : "r"(addr));                                               \
            }                                                                   \
            _Pragma("unroll")                                                   \
            for (int np = 0; np < 4; np++) {                                    \
                const unsigned addr =                                           \
                    baseB + (unsigned)(((wn + np * 16 + bRow) * LDH + kk + bColH) << 1); \
                asm volatile(                                                   \
                    "ldmatrix.sync.aligned.m8n8.x4.shared.b16 {%0,%1,%2,%3}, [%4];" \
                    : "=r"(b[2 * np][0]), "=r"(b[2 * np][1]),                   \
                      "=r"(b[2 * np + 1][0]), "=r"(b[2 * np + 1][1])            \
                    : "r"(addr));                                               \
            }                                                                   \
            _Pragma("unroll")                                                   \
            for (int mi = 0; mi < 4; mi++)                                      \
                _Pragma("unroll")                                               \
                for (int ni = 0; ni < 8; ni++)                                  \
                    mma_fp16(acc[mi][ni], a[mi], b[ni]);                        \
        }                                                                       \
    }                                                                           \
    const int gid = lane >> 2;                                                  \
    const int tig = lane & 3;

// ================= plain big GEMM (fp32 out, up to 2 biases) =================
__global__ __launch_bounds__(128, 2)
void gemm_big4(const __half* __restrict__ A, int lda,
               const __half* __restrict__ W, int ldw,
               const float* __restrict__ bias1, const float* __restrict__ bias2,
               float* __restrict__ C, int ldc, int kIters)
{
    GEMM4_PROLOG();
#pragma unroll
    for (int mi = 0; mi < 4; mi++) {
#pragma unroll
        for (int ni = 0; ni < 8; ni++) {
            const int col = n0 + wn + ni * 8 + tig * 2;
            float b0 = bias1[col];
            float b1 = bias1[col + 1];
            if (bias2) { b0 += bias2[col]; b1 += bias2[col + 1]; }
            const int r0 = m0 + wm + mi * 16 + gid;
            const int r1 = r0 + 8;
            *reinterpret_cast<float2*>(&C[(long)r0 * ldc + col]) =
                make_float2(acc[mi][ni][0] + b0, acc[mi][ni][1] + b1);
            *reinterpret_cast<float2*>(&C[(long)r1 * ldc + col]) =
                make_float2(acc[mi][ni][2] + b0, acc[mi][ni][3] + b1);
        }
    }
}

// ================= gin GEMM with fused GRU epilogue =================
// acc = x @ W_ih_n^T (pre-bias). Epilogue computes full GRU update.
__global__ __launch_bounds__(128, 2)
void gemm_gru(const __half* __restrict__ A, int lda,
              const __half* __restrict__ W, int ldw,
              const float* __restrict__ bias_n,      // b_ih + 4096
              const float* __restrict__ gsum,        // [B,4096] r,z (bias incl)
              const float* __restrict__ ghn,         // [B,2048] h_n (bias incl)
              const float* __restrict__ state,       // fp32, row stride 2304
              float* __restrict__ outHidden,         // d_out + B*32
              __half* __restrict__ lasth,            // h1 -> cols 2048: of lasth
              int kIters)
{
    GEMM4_PROLOG();
#pragma unroll
    for (int mi = 0; mi < 4; mi++) {
#pragma unroll
        for (int ni = 0; ni < 8; ni++) {
            const int col = n0 + wn + ni * 8 + tig * 2;   // [0,2048)
            const float bn0 = bias_n[col];
            const float bn1 = bias_n[col + 1];
#pragma unroll
            for (int half = 0; half < 2; half++) {
                const int row = m0 + wm + mi * 16 + gid + half * 8;
                const float in0 = acc[mi][ni][half * 2 + 0] + bn0;
                const float in1 = acc[mi][ni][half * 2 + 1] + bn1;
                const float2 sr = *reinterpret_cast<const float2*>(
                    &gsum[(long)row * 4096 + col]);
                const float2 sz = *reinterpret_cast<const float2*>(
                    &gsum[(long)row * 4096 + 2048 + col]);
                const float2 hn = *reinterpret_cast<const float2*>(
                    &ghn[(long)row * 2048 + col]);
                const float2 h0 = *reinterpret_cast<const float2*>(
                    &state[(long)row * 2304 + 256 + col]);
                const float r0 = sigm(sr.x), r1 = sigm(sr.y);
                const float z0 = sigm(sz.x), z1 = sigm(sz.y);
                const float n0f = tanhf(in0 + r0 * hn.x);
                const float n1f = tanhf(in1 + r1 * hn.y);
                const float h1a = (1.0f - z0) * n0f + z0 * h0.x;
                const float h1b = (1.0f - z1) * n1f + z1 * h0.y;
                *reinterpret_cast<float2*>(&outHidden[(long)row * 2048 + col]) =
                    make_float2(0.5f * (h0.x + h1a), 0.5f * (h0.y + h1b));
                *reinterpret_cast<__half2*>(&lasth[(long)row * 4096 + 2048 + col]) =
                    __floats2half2_rn(h1a, h1b);
            }
        }
    }
}

// ================= fused feature GEMM: A=env, W=[W_o;W_post] (N=4096) ============
__global__ __launch_bounds__(256, 2)
void gemm_feat(const __half* __restrict__ A, int lda,
               const __half* __restrict__ W, int ldw,
               const float* __restrict__ bias0, const float* __restrict__ bias1,
               __half* __restrict__ C0, int ldc0,
               __half* __restrict__ C1, int ldc1, int kIters)
{
    constexpr int BM = 128, BK = 64, LDH = 72, STAGES = 3;
    constexpr int OPB = BM * LDH * 2;
    extern __shared__ __half smh[];
    const unsigned sA = smem_u32(smh);
    const unsigned sB = sA + STAGES * OPB;

    const int m0 = blockIdx.y * BM;
    const int n0 = blockIdx.x * 128;
    const int nloc = (n0 < 2048) ? n0 : (n0 - 2048);
    const float* bias = (n0 < 2048) ? bias0 : bias1;
    __half* C = (n0 < 2048) ? C0 : C1;
    const int ldc = (n0 < 2048) ? ldc0 : ldc1;

    const int tid = threadIdx.x;
    const int warp = tid >> 5;
    const int lane = tid & 31;
    const int wm = (warp & 1) * 64;
    const int wn = (warp >> 1) * 32;

    const int g = lane >> 3;
    const int r8 = lane & 7;
    const int aRow = (g & 1) * 8 + r8;
    const int aColH = (g >> 1) * 8;
    const int bRow = (g >> 1) * 8 + r8;
    const int bColH = (g & 1) * 8;

    float acc[4][4][4];
#pragma unroll
    for (int i = 0; i < 4; i++)
#pragma unroll
        for (int j = 0; j < 4; j++)
#pragma unroll
            for (int v = 0; v < 4; v++) acc[i][j][v] = 0.0f;

    auto issueStage = [&](int it, int stage) {
        if (it < kIters) {
            const long k0 = (long)it * BK;
            const unsigned dA = sA + stage * OPB;
            const unsigned dB = sB + stage * OPB;
#pragma unroll
            for (int i = 0; i < 4; i++) {
                const int ch = tid + i * 256;
                const int r = ch >> 3, c = ch & 7;
                const __half* src = A + (long)(m0 + r) * lda + k0 + c * 8;
                const unsigned dst = dA + (unsigned)(r * LDH + c * 8) * 2u;
                asm volatile("cp.async.cg.shared.global [%0], [%1], 16;\n"
                             :: "r"(dst), "l"(src));
            }
#pragma unroll
            for (int i = 0; i < 4; i++) {
                const int ch = tid + i * 256;
                const int r = ch >> 3, c = ch & 7;
                const __half* src = W + (long)(n0 + r) * ldw + k0 + c * 8;
                const unsigned dst = dB + (unsigned)(r * LDH + c * 8) * 2u;
                asm volatile("cp.async.cg.shared.global [%0], [%1], 16;\n"
                             :: "r"(dst), "l"(src));
            }
        }
        asm volatile("cp.async.commit_group;\n");
    };

    issueStage(0, 0);
    issueStage(1, 1);

    for (int it = 0; it < kIters; it++) {
        asm volatile("cp.async.wait_group 1;\n");
        __syncthreads();
        const int stage = it % STAGES;
        issueStage(it + 2, (it + 2) % STAGES);

        const unsigned baseA = sA + stage * OPB;
        const unsigned baseB = sB + stage * OPB;

#pragma unroll
        for (int kk = 0; kk < BK; kk += 16) {
            unsigned a[4][4], b[4][2];
#pragma unroll
            for (int mi = 0; mi < 4; mi++) {
                const unsigned addr =
                    baseA + (unsigned)(((wm + mi * 16 + aRow) * LDH + kk + aColH) << 1);
                asm volatile(
                    "ldmatrix.sync.aligned.m8n8.x4.shared.b16 {%0,%1,%2,%3}, [%4];"
                    : "=r"(a[mi][0]), "=r"(a[mi][1]), "=r"(a[mi][2]), "=r"(a[mi][3])
                    : "r"(addr));
            }
#pragma unroll
            for (int np = 0; np < 2; np++) {
                const unsigned addr =
                    baseB + (unsigned)(((wn + np * 16 + bRow) * LDH + kk + bColH) << 1);
                asm volatile(
                    "ldmatrix.sync.aligned.m8n8.x4.shared.b16 {%0,%1,%2,%3}, [%4];"
                    : "=r"(b[2 * np][0]), "=r"(b[2 * np][1]),
                      "=r"(b[2 * np + 1][0]), "=r"(b[2 * np + 1][1])
                    : "r"(addr));
            }
#pragma unroll
            for (int mi = 0; mi < 4; mi++)
#pragma unroll
                for (int ni = 0; ni < 4; ni++)
                    mma_fp16(acc[mi][ni], a[mi], b[ni]);
        }
    }

    const int gid = lane >> 2;
    const int tig = lane & 3;
#pragma unroll
    for (int mi = 0; mi < 4; mi++) {
#pragma unroll
        for (int ni = 0; ni < 4; ni++) {
            const int col = nloc + wn + ni * 8 + tig * 2;
            const float b0 = bias[col];
            const float b1 = bias[col + 1];
            const int r0 = m0 + wm + mi * 16 + gid;
            const int r1 = r0 + 8;
            const float v00 = fmaxf(acc[mi][ni][0] + b0, 0.f);
            const float v01 = fmaxf(acc[mi][ni][1] + b1, 0.f);
            const float v10 = fmaxf(acc[mi][ni][2] + b0, 0.f);
            const float v11 = fmaxf(acc[mi][ni][3] + b1, 0.f);
            *reinterpret_cast<__half2*>(&C[(long)r0 * ldc + col]) =
                __floats2half2_rn(v00, v01);
            *reinterpret_cast<__half2*>(&C[(long)r1 * ldc + col]) =
                __floats2half2_rn(v10, v11);
        }
    }
}

// ================= action head (fp16, N=32, tanh) =================
__global__ __launch_bounds__(256)
void gemm_head_h(const __half* __restrict__ A, int lda,
                 const __half* __restrict__ W, int ldw,
                 const float* __restrict__ bias,
                 float* __restrict__ C, int K)
{
    constexpr int BM = 128, BN = 32, BK = 64, LDH = 72;
    __shared__ __align__(16) __half As[BM * LDH];
    __shared__ __align__(16) __half Bs[BN * LDH];
    const unsigned sA = smem_u32(As);
    const unsigned sB = smem_u32(Bs);

    const int m0 = blockIdx.y * BM;
    const int tid = threadIdx.x;
    const int warp = tid >> 5;
    const int lane = tid & 31;
    const int wm = warp * 16;

    const int g = lane >> 3;
    const int r8 = lane & 7;
    const int aRow = (g & 1) * 8 + r8;
    const int aColH = (g >> 1) * 8;
    const int bRow = (g >> 1) * 8 + r8;
    const int bColH = (g & 1) * 8;

    float acc[4][4];
#pragma unroll
    for (int j = 0; j < 4; j++)
#pragma unroll
        for (int v = 0; v < 4; v++) acc[j][v] = 0.0f;

    for (int k0 = 0; k0 < K; k0 += BK) {
#pragma unroll
        for (int i = 0; i < 4; i++) {
            const int ch = tid + i * 256;
            const int r = ch >> 3, c = ch & 7;
            *reinterpret_cast<uint4*>(&As[r * LDH + c * 8]) =
                *reinterpret_cast<const uint4*>(&A[(long)(m0 + r) * lda + k0 + c * 8]);
        }
        {
            const int r = tid >> 3, c = tid & 7;
            if (r < BN)
                *reinterpret_cast<uint4*>(&Bs[r * LDH + c * 8]) =
                    *reinterpret_cast<const uint4*>(&W[(long)r * ldw + k0 + c * 8]);
        }
        __syncthreads();

#pragma unroll
        for (int kk = 0; kk < BK; kk += 16) {
            unsigned a[4], b[4][2];
            {
                const unsigned addr = sA + (unsigned)(((wm + aRow) * LDH + kk + aColH) << 1);
                asm volatile(
                    "ldmatrix.sync.aligned.m8n8.x4.shared.b16 {%0,%1,%2,%3}, [%4];"
                    : "=r"(a[0]), "=r"(a[1]), "=r"(a[2]), "=r"(a[3]) : "r"(addr));
            }
#pragma unroll
            for (int np = 0; np < 2; np++) {
                const unsigned addr = sB + (unsigned)(((np * 16 + bRow) * LDH + kk + bColH) << 1);
                asm volatile(
                    "ldmatrix.sync.aligned.m8n8.x4.shared.b16 {%0,%1,%2,%3}, [%4];"
                    : "=r"(b[2 * np][0]), "=r"(b[2 * np][1]),
                      "=r"(b[2 * np + 1][0]), "=r"(b[2 * np + 1][1])
                    : "r"(addr));
            }
#pragma unroll
            for (int ni = 0; ni < 4; ni++)
                mma_fp16(acc[ni], a, b[ni]);
        }
        __syncthreads();
    }

    const int gid = lane >> 2;
    const int tig = lane & 3;
#pragma unroll
    for (int ni = 0; ni < 4; ni++) {
        const int col = ni * 8 + tig * 2;
        const float b0 = bias[col];
        const float b1 = bias[col + 1];
        const int r0 = m0 + wm + gid;
        const int r1 = r0 + 8;
        C[(long)r0 * 32 + col]     = tanhf(acc[ni][0] + b0);
        C[(long)r0 * 32 + col + 1] = tanhf(acc[ni][1] + b1);
        C[(long)r1 * 32 + col]     = tanhf(acc[ni][2] + b0);
        C[(long)r1 * 32 + col + 1] = tanhf(acc[ni][3] + b1);
    }
}

// ================= conversion kernels =================
__global__ __launch_bounds__(256)
void cvt_half(const float* __restrict__ in, __half* __restrict__ out, int n4)
{
    const int i = blockIdx.x * blockDim.x + threadIdx.x;
    if (i < n4) {
        const float4 v = reinterpret_cast<const float4*>(in)[i];
        reinterpret_cast<__half2*>(out)[2 * i]     = __floats2half2_rn(v.x, v.y);
        reinterpret_cast<__half2*>(out)[2 * i + 1] = __floats2half2_rn(v.z, v.w);
    }
}

// strided cvt: in [rows][inK] contiguous -> out rows with stride ldout (halves)
__global__ __launch_bounds__(256)
void cvt_half_stride(const float* __restrict__ in, __half* __restrict__ out,
                     int rows, int inK, int ldout)
{
    const int i = blockIdx.x * blockDim.x + threadIdx.x;   // rows*(inK/4)
    const int perRow = inK >> 2;
    if (i >= rows * perRow) return;
    const int row = i / perRow;
    const int c4 = (i % perRow) * 4;
    const float4 v = *reinterpret_cast<const float4*>(in + (long)row * inK + c4);
    __half* dst = out + (long)row * ldout + c4;
    *reinterpret_cast<__half2*>(dst)     = __floats2half2_rn(v.x, v.y);
    *reinterpret_cast<__half2*>(dst + 2) = __floats2half2_rn(v.z, v.w);
}

__global__ __launch_bounds__(256)
void cvt_half_pad(const float* __restrict__ in, __half* __restrict__ out,
                  int rows, int inK, int outK)
{
    const int i = blockIdx.x * blockDim.x + threadIdx.x;
    const int perRow = outK >> 2;
    if (i >= rows * perRow) return;
    const int row = i / perRow;
    const int c4 = (i % perRow) * 4;
    __half2 h0, h1;
    if (c4 < inK) {
        const float4 v = *reinterpret_cast<const float4*>(in + (long)row * inK + c4);
        h0 = __floats2half2_rn(v.x, v.y);
        h1 = __floats2half2_rn(v.z, v.w);
    } else {
        h0 = __floats2half2_rn(0.f, 0.f);
        h1 = h0;
    }
    *reinterpret_cast<__half2*>(out + (long)row * outK + c4)     = h0;
    *reinterpret_cast<__half2*>(out + (long)row * outK + c4 + 2) = h1;
}

// split state -> env fp16 [B,256] and h0 fp16 into xfull cols [4096,6144)
__global__ __launch_bounds__(256)
void split_state_kernel(const float* __restrict__ state,
                        __half* __restrict__ envh, __half* __restrict__ xfull)
{
    const int i = blockIdx.x * blockDim.x + threadIdx.x;
    if (i >= B_ * 576) return;
    const int row = i / 576;
    const int c4 = (i % 576) * 4;
    const float4 v = *reinterpret_cast<const float4*>(state + (long)row * 2304 + c4);
    const __half2 h0 = __floats2half2_rn(v.x, v.y);
    const __half2 h1 = __floats2half2_rn(v.z, v.w);
    __half* dst = (c4 < 256) ? (envh + (long)row * 256 + c4)
                             : (xfull + (long)row * 6144 + 4096 + (c4 - 256));
    *reinterpret_cast<__half2*>(dst)     = h0;
    *reinterpret_cast<__half2*>(dst + 2) = h1;
}

extern "C" void kernel_launch(void* const* d_in, const int* in_sizes, int n_in,
                              void* d_out, int out_size)
{
    const float* state  = (const float*)d_in[0];
    const float* pa     = (const float*)d_in[1];
    const float* W_o    = (const float*)d_in[2];
    const float* b_o    = (const float*)d_in[3];
    const float* W_a    = (const float*)d_in[4];
    const float* b_a    = (const float*)d_in[5];
    const float* W_post = (const float*)d_in[6];
    const float* b_post = (const float*)d_in[7];
    const float* W_ih   = (const float*)d_in[8];
    const float* W_hh   = (const float*)d_in[9];
    const float* b_ih   = (const float*)d_in[10];
    const float* b_hh   = (const float*)d_in[11];
    const float* W3     = (const float*)d_in[12];
    const float* b3     = (const float*)d_in[13];
    float* out = (float*)d_out;

    float *gsum, *ghn;
    __half *xfull, *lasth, *Wrz, *Wihn, *Whhn, *envh, *pah, *Woph, *Wah, *W3h;
    cudaGetSymbolAddress((void**)&xfull,  g_xfull);
    cudaGetSymbolAddress((void**)&gsum,   g_gsum);
    cudaGetSymbolAddress((void**)&ghn,    g_ghn);
    cudaGetSymbolAddress((void**)&lasth,  g_lasth);
    cudaGetSymbolAddress((void**)&Wrz,    g_Wrz);
    cudaGetSymbolAddress((void**)&Wihn,   g_Wihn);
    cudaGetSymbolAddress((void**)&Whhn,   g_Whhn);
    cudaGetSymbolAddress((void**)&envh,   g_envh);
    cudaGetSymbolAddress((void**)&pah,    g_pah);
    cudaGetSymbolAddress((void**)&Woph,   g_Woph);
    cudaGetSymbolAddress((void**)&Wah,    g_Wah);
    cudaGetSymbolAddress((void**)&W3h,    g_W3h);

    const int SMEMH = 3 * 2 * 128 * 72 * 2;   // 110592 B
    cudaFuncSetAttribute(gemm_feat, cudaFuncAttributeMaxDynamicSharedMemorySize, SMEMH);
    cudaFuncSetAttribute(gemm_big4, cudaFuncAttributeMaxDynamicSharedMemorySize, SMEMH);
    cudaFuncSetAttribute(gemm_gru,  cudaFuncAttributeMaxDynamicSharedMemorySize, SMEMH);

    const dim3 blk(256);

    // 0: split (env + h0 into xfull)
    split_state_kernel<<<(B_ * 576 + 255) / 256, blk>>>(state, envh, xfull);
    // 1: W_hh n-gate rows [4096:6144) -> Whhn (contiguous K=2048)
    cvt_half<<<(2048 * 2048 / 4 + 255) / 256, blk>>>(W_hh + (size_t)4096 * 2048, Whhn,
                                                     2048 * 2048 / 4);
    // 2: pa pad
    cvt_half_pad<<<(B_ * 16 + 255) / 256, blk>>>(pa, pah, B_, 32, 64);

    // 3: ghn = h0 @ W_hh_n^T + b_hh_n   (profiled)
    gemm_big4<<<dim3(16, 64), dim3(128), SMEMH>>>(xfull + 4096, 6144, Whhn, 2048,
                                                  b_hh + 4096, nullptr, ghn, 2048, 32);

    // rz combined weights: [W_ih_rz | W_hh_rz] rows 0..4095, K=6144
    cvt_half_stride<<<(4096 * 1024 + 255) / 256, blk>>>(W_ih, Wrz, 4096, 4096, 6144);
    cvt_half_stride<<<(4096 * 512 + 255) / 256, blk>>>(W_hh, Wrz + 4096, 4096, 2048, 6144);
    // W_ih n-gate rows
    cvt_half<<<(2048 * 4096 / 4 + 255) / 256, blk>>>(W_ih + (size_t)4096 * 4096, Wihn,
                                                     2048 * 4096 / 4);
    // feature weights
    cvt_half<<<(2048 * 256 / 4 + 255) / 256, blk>>>(W_o, Woph, 2048 * 256 / 4);
    cvt_half<<<(2048 * 256 / 4 + 255) / 256, blk>>>(W_post, Woph + (size_t)2048 * 256,
                                                    2048 * 256 / 4);
    cvt_half_pad<<<(2048 * 16 + 255) / 256, blk>>>(W_a, Wah, 2048, 32, 64);

    // features: feat_o -> xfull[:,0:2048], feat_post -> lasth[:,0:2048]
    gemm_feat<<<dim3(32, 64), blk, SMEMH>>>(envh, 256, Woph, 256, b_o, b_post,
                                            xfull, 6144, lasth, 4096, 4);
    // feat_a -> xfull[:,2048:4096]  (via gemm_feat path with coff handled by C0 offset)
    gemm_feat<<<dim3(16, 64), blk, SMEMH>>>(pah, 64, Wah, 64, b_a, b_a,
                                            xfull + 2048, 6144, nullptr, 0, 1);

    // gsum = [x|h0] @ Wrz^T + (b_ih+b_hh)[0:4096]
    gemm_big4<<<dim3(32, 64), dim3(128), SMEMH>>>(xfull, 6144, Wrz, 6144,
                                                  b_ih, b_hh, gsum, 4096, 96);

    // gin GEMM + fused GRU epilogue
    gemm_gru<<<dim3(16, 64), dim3(128), SMEMH>>>(xfull, 6144, Wihn, 4096,
                                                 b_ih + 4096, gsum, ghn, state,
                                                 out + (size_t)B_ * DA_,
                                                 lasth, 64);

    // action head
    cvt_half<<<(32 * 4096 / 4 + 255) / 256, blk>>>(W3, W3h, 32 * 4096 / 4);
    gemm_head_h<<<dim3(1, 64), blk>>>(lasth, 4096, W3h, 4096, b3, out, 4096);
}